// round 1
// baseline (speedup 1.0000x reference)
#include <cuda_runtime.h>
#include <math.h>

// GAT forward, B=4 N=2048 F=128 H=8 D=64 C=32.
// Trick: exp(leakyrelu(f1_i+f2_j)) / exp(f1_i) = cond ? exp(f2_j) : exp(-0.8 f1_i)*exp(0.2 f2_j)
// -> softmax numerator/denominator share the exp(f1_i) factor, which cancels.
// So the inner loop is: compare + select + bitmask test + D fp32x2 FMAs. No exp inside.

#define BB 4
#define NN 2048
#define FF 128
#define DD 64
#define HH 8
#define CC 32
#define HD (HH*DD)

__device__ __align__(16) float  g_Wh[BB*HH*NN*DD];   // [b,h,n,d] 16MB
__device__ __align__(16) float2 g_F1R[BB*HH*NN];     // (f1, exp(-0.8 f1))
__device__ __align__(16) float4 g_F2C[BB*HH*NN];     // (f2, exp(f2), exp(0.2 f2), 0)
__device__ __align__(16) float  g_h[BB*NN*HD];       // [b,n,h*64+d] 16MB
__device__ __align__(16) float  g_Wh2[BB*NN*CC];     // [b,n,c]
__device__ __align__(16) float2 g_G1R[BB*NN];
__device__ __align__(16) float4 g_G2C[BB*NN];

typedef unsigned long long u64;

__device__ __forceinline__ u64 dup2(float x) {
    u64 r; asm("mov.b64 %0, {%1, %1};" : "=l"(r) : "f"(x)); return r;
}
__device__ __forceinline__ void fma2(u64& d, u64 a, u64 b) {
    asm("fma.rn.f32x2 %0, %1, %2, %0;" : "+l"(d) : "l"(a), "l"(b));
}
__device__ __forceinline__ float2 unp(u64 v) {
    float2 r; asm("mov.b64 {%0, %1}, %2;" : "=f"(r.x), "=f"(r.y) : "l"(v)); return r;
}

// ---------------- K1: Wh[b,h,n,d] = x[b,n,:] @ W[h,:,d] ----------------
// X[8192,128] @ Wcat[128,512]; BM=64 BN=128 BK=32, 256 thr, 4x8 micro (f32x2).
__global__ __launch_bounds__(256) void k1_gemm_wh(const float* __restrict__ x,
                                                  const float* __restrict__ W) {
    __shared__ __align__(16) float Xs[64*33];
    __shared__ __align__(16) float Ws[32*128];
    int t = threadIdx.x;
    int tr = t >> 4, tc = t & 15;
    int gr0 = blockIdx.y * 64;
    int gc0 = blockIdx.x * 128;
    u64 acc[4][4];
    #pragma unroll
    for (int i=0;i<4;i++){ acc[i][0]=0; acc[i][1]=0; acc[i][2]=0; acc[i][3]=0; }

    for (int kt = 0; kt < 4; kt++) {
        int k0 = kt*32;
        for (int idx = t; idx < 2048; idx += 256) {
            int row = idx >> 5, kk = idx & 31;
            Xs[row*33 + kk] = x[(gr0+row)*FF + k0 + kk];
        }
        for (int idx = t; idx < 4096; idx += 256) {
            int kk = idx >> 7, c = idx & 127;
            int gc = gc0 + c;
            Ws[idx] = W[(gc>>6)*(FF*DD) + (k0+kk)*DD + (gc&63)];
        }
        __syncthreads();
        #pragma unroll
        for (int kk = 0; kk < 32; kk++) {
            u64 ad[4];
            #pragma unroll
            for (int i=0;i<4;i++) ad[i] = dup2(Xs[(tr*4+i)*33 + kk]);
            const ulonglong2* bp = reinterpret_cast<const ulonglong2*>(&Ws[kk*128 + tc*8]);
            ulonglong2 b01 = bp[0], b23 = bp[1];
            #pragma unroll
            for (int i=0;i<4;i++) {
                fma2(acc[i][0], ad[i], b01.x);
                fma2(acc[i][1], ad[i], b01.y);
                fma2(acc[i][2], ad[i], b23.x);
                fma2(acc[i][3], ad[i], b23.y);
            }
        }
        __syncthreads();
    }
    #pragma unroll
    for (int i=0;i<4;i++) {
        int gr = gr0 + tr*4 + i;
        int b = gr >> 11, n = gr & 2047;
        #pragma unroll
        for (int j=0;j<4;j++) {
            float2 v = unp(acc[i][j]);
            int gc = gc0 + tc*8 + j*2;
            int h = gc >> 6, d = gc & 63;
            float* o = &g_Wh[(((b<<3)|h)*NN + n)*DD + d];
            o[0] = v.x; o[1] = v.y;
        }
    }
}

// ---------------- K2: f1,f2 and exp precompute ----------------
__global__ __launch_bounds__(256) void k2_f(const float* __restrict__ a1,
                                            const float* __restrict__ a2) {
    int tid = blockIdx.x*256 + threadIdx.x;      // 0..65535 = (b*8+h)*2048+n
    int h = (tid >> 11) & 7;
    const float4* wr = reinterpret_cast<const float4*>(&g_Wh[tid*DD]);
    const float4* p1 = reinterpret_cast<const float4*>(&a1[h*DD]);
    const float4* p2 = reinterpret_cast<const float4*>(&a2[h*DD]);
    float f1=0.f, f2=0.f;
    #pragma unroll
    for (int i=0;i<16;i++) {
        float4 w = wr[i], v1 = p1[i], v2 = p2[i];
        f1 += w.x*v1.x + w.y*v1.y + w.z*v1.z + w.w*v1.w;
        f2 += w.x*v2.x + w.y*v2.y + w.z*v2.z + w.w*v2.w;
    }
    g_F1R[tid] = make_float2(f1, expf(-0.8f*f1));
    g_F2C[tid] = make_float4(f2, expf(f2), expf(0.2f*f2), 0.f);
}

// ---------------- K3: h = elu(softmax(mask(e)) @ Wh) ----------------
// CTA = (64 i-rows, one head, one batch). TJ=128. 256 thr = 64 rows x 4 dgroups(16 dims).
__global__ __launch_bounds__(256) void k3_attn1(const int* __restrict__ adj) {
    __shared__ __align__(16) float Whs[128*64];
    __shared__ __align__(16) float4 f2c[128];
    __shared__ unsigned adjb[64*4];
    int t = threadIdx.x;
    int il = t >> 2, dg = t & 3;
    int i0 = blockIdx.x * 64;
    int h = blockIdx.y, b = blockIdx.z;
    int bh = b*HH + h;
    const float* whbase = &g_Wh[(size_t)bh*NN*DD];
    float2 f1r = g_F1R[bh*NN + i0 + il];
    float negf1 = -f1r.x, rmul = f1r.y;
    u64 acc[8];
    #pragma unroll
    for (int i=0;i<8;i++) acc[i]=0ull;
    float z = 0.f;
    int warp = t >> 5, lane = t & 31;

    for (int jt = 0; jt < 16; jt++) {
        int j0 = jt * 128;
        for (int idx = t; idx < 8192; idx += 256)
            Whs[idx] = whbase[j0*DD + idx];
        if (t < 128) f2c[t] = g_F2C[bh*NN + j0 + t];
        #pragma unroll
        for (int rrow = 0; rrow < 8; rrow++) {
            int row = warp*8 + rrow;
            const int* ar = adj + ((b*NN + i0 + row)*NN + j0);
            #pragma unroll
            for (int ww = 0; ww < 4; ww++) {
                int v = ar[ww*32 + lane];
                unsigned m = __ballot_sync(0xffffffffu, v > 0);
                if (lane == 0) adjb[row*4 + ww] = m;
            }
        }
        __syncthreads();
        #pragma unroll
        for (int w = 0; w < 4; w++) {
            unsigned bw = adjb[il*4 + w];
            #pragma unroll
            for (int kk = 0; kk < 32; kk++) {
                int jj = w*32 + kk;
                float4 fc = f2c[jj];
                float w1 = (fc.x > negf1) ? fc.y : rmul*fc.z;
                float wv = (bw & (1u<<kk)) ? w1 : 0.f;
                z += wv;
                u64 wd = dup2(wv);
                const ulonglong2* wp = reinterpret_cast<const ulonglong2*>(&Whs[jj*64 + dg*16]);
                ulonglong2 p0 = wp[0], p1 = wp[1], p2 = wp[2], p3 = wp[3];
                fma2(acc[0], wd, p0.x); fma2(acc[1], wd, p0.y);
                fma2(acc[2], wd, p1.x); fma2(acc[3], wd, p1.y);
                fma2(acc[4], wd, p2.x); fma2(acc[5], wd, p2.y);
                fma2(acc[6], wd, p3.x); fma2(acc[7], wd, p3.y);
            }
        }
        __syncthreads();
    }
    if (z < 1e-30f) z = 1.f;
    float invz = 1.f / z;
    float out[16];
    #pragma unroll
    for (int i=0;i<8;i++) {
        float2 v = unp(acc[i]);
        float a = v.x * invz, c = v.y * invz;
        out[2*i]   = a > 0.f ? a : expm1f(a);   // ELU alpha=1
        out[2*i+1] = c > 0.f ? c : expm1f(c);
    }
    float4* op = reinterpret_cast<float4*>(&g_h[((b*NN) + i0 + il)*HD + h*DD + dg*16]);
    op[0] = *(float4*)&out[0];
    op[1] = *(float4*)&out[4];
    op[2] = *(float4*)&out[8];
    op[3] = *(float4*)&out[12];
}

// ---------------- K4: Wh2 = h[8192,512] @ Wo[512,32] ----------------
__global__ __launch_bounds__(256) void k4_gemm_out(const float* __restrict__ Wo) {
    __shared__ __align__(16) float hs[64*68];
    __shared__ __align__(16) float Wos[64*32];
    int t = threadIdx.x;
    int r = t >> 2, cg = t & 3;
    int gr0 = blockIdx.x * 64;
    u64 acc[4] = {0,0,0,0};
    for (int kt = 0; kt < 8; kt++) {
        int k0 = kt*64;
        for (int idx = t; idx < 4096; idx += 256) {
            int row = idx >> 6, kk = idx & 63;
            hs[row*68 + kk] = g_h[(gr0+row)*HD + k0 + kk];
        }
        for (int idx = t; idx < 2048; idx += 256)
            Wos[idx] = Wo[k0*32 + idx];
        __syncthreads();
        #pragma unroll
        for (int kk = 0; kk < 64; kk++) {
            u64 ad = dup2(hs[r*68 + kk]);
            const ulonglong2* bp = reinterpret_cast<const ulonglong2*>(&Wos[kk*32 + cg*8]);
            ulonglong2 b01 = bp[0], b23 = bp[1];
            fma2(acc[0], ad, b01.x); fma2(acc[1], ad, b01.y);
            fma2(acc[2], ad, b23.x); fma2(acc[3], ad, b23.y);
        }
        __syncthreads();
    }
    float o[8];
    #pragma unroll
    for (int i=0;i<4;i++){ float2 v = unp(acc[i]); o[2*i]=v.x; o[2*i+1]=v.y; }
    float4* op = reinterpret_cast<float4*>(&g_Wh2[(gr0 + r)*CC + cg*8]);
    op[0] = *(float4*)&o[0]; op[1] = *(float4*)&o[4];
}

// ---------------- K4b: g1,g2 + exp precompute ----------------
__global__ __launch_bounds__(256) void k4b_g(const float* __restrict__ ao1,
                                             const float* __restrict__ ao2) {
    int tid = blockIdx.x*256 + threadIdx.x;  // 0..8191
    const float4* wr = reinterpret_cast<const float4*>(&g_Wh2[tid*CC]);
    const float4* p1 = reinterpret_cast<const float4*>(ao1);
    const float4* p2 = reinterpret_cast<const float4*>(ao2);
    float g1=0.f, g2=0.f;
    #pragma unroll
    for (int i=0;i<8;i++) {
        float4 w = wr[i], v1=p1[i], v2=p2[i];
        g1 += w.x*v1.x + w.y*v1.y + w.z*v1.z + w.w*v1.w;
        g2 += w.x*v2.x + w.y*v2.y + w.z*v2.z + w.w*v2.w;
    }
    g_G1R[tid] = make_float2(g1, expf(-0.8f*g1));
    g_G2C[tid] = make_float4(g2, expf(g2), expf(0.2f*g2), 0.f);
}

// ---------------- K5: out = softmax(mask(e2)) @ Wh2 ----------------
__global__ __launch_bounds__(256) void k5_attn2(const int* __restrict__ adj,
                                                float* __restrict__ out) {
    __shared__ __align__(16) float Ws2[128*32];
    __shared__ __align__(16) float4 g2c[128];
    __shared__ unsigned adjb[64*4];
    int t = threadIdx.x;
    int il = t >> 2, dg = t & 3;
    int i0 = blockIdx.x * 64;
    int b = blockIdx.y;
    float2 g1r = g_G1R[b*NN + i0 + il];
    float negg = -g1r.x, rmul = g1r.y;
    u64 acc[4] = {0,0,0,0};
    float z = 0.f;
    int warp = t>>5, lane = t&31;

    for (int jt = 0; jt < 16; jt++) {
        int j0 = jt*128;
        for (int idx = t; idx < 4096; idx += 256)
            Ws2[idx] = g_Wh2[(b*NN + j0)*CC + idx];
        if (t < 128) g2c[t] = g_G2C[b*NN + j0 + t];
        #pragma unroll
        for (int rrow = 0; rrow < 8; rrow++) {
            int row = warp*8 + rrow;
            const int* ar = adj + ((b*NN + i0 + row)*NN + j0);
            #pragma unroll
            for (int ww = 0; ww < 4; ww++) {
                int v = ar[ww*32 + lane];
                unsigned m = __ballot_sync(0xffffffffu, v > 0);
                if (lane == 0) adjb[row*4 + ww] = m;
            }
        }
        __syncthreads();
        #pragma unroll
        for (int w = 0; w < 4; w++) {
            unsigned bw = adjb[il*4 + w];
            #pragma unroll
            for (int kk = 0; kk < 32; kk++) {
                int jj = w*32 + kk;
                float4 fc = g2c[jj];
                float w1 = (fc.x > negg) ? fc.y : rmul*fc.z;
                float wv = (bw & (1u<<kk)) ? w1 : 0.f;
                z += wv;
                u64 wd = dup2(wv);
                const ulonglong2* wp = reinterpret_cast<const ulonglong2*>(&Ws2[jj*32 + dg*8]);
                ulonglong2 p0 = wp[0], p1 = wp[1];
                fma2(acc[0], wd, p0.x); fma2(acc[1], wd, p0.y);
                fma2(acc[2], wd, p1.x); fma2(acc[3], wd, p1.y);
            }
        }
        __syncthreads();
    }
    if (z < 1e-30f) z = 1.f;
    float invz = 1.f/z;
    float o[8];
    #pragma unroll
    for (int i=0;i<4;i++){ float2 v=unp(acc[i]); o[2*i]=v.x*invz; o[2*i+1]=v.y*invz; }
    float4* op = reinterpret_cast<float4*>(&out[((b*NN)+i0+il)*CC + dg*8]);
    op[0] = *(float4*)&o[0]; op[1] = *(float4*)&o[4];
}

extern "C" void kernel_launch(void* const* d_in, const int* in_sizes, int n_in,
                              void* d_out, int out_size) {
    const float* x   = (const float*)d_in[0];
    const int*   adj = (const int*)  d_in[1];
    const float* W   = (const float*)d_in[2];
    const float* a1  = (const float*)d_in[3];
    const float* a2  = (const float*)d_in[4];
    const float* Wo  = (const float*)d_in[5];
    const float* ao1 = (const float*)d_in[6];
    const float* ao2 = (const float*)d_in[7];
    float* out = (float*)d_out;

    k1_gemm_wh<<<dim3(4,128), 256>>>(x, W);        // Wh
    k2_f<<<256, 256>>>(a1, a2);                    // f1,f2 + exps
    k3_attn1<<<dim3(32, 8, 4), 256>>>(adj);        // layer-1 attention + ELU
    k4_gemm_out<<<128, 256>>>(Wo);                 // Wh2 = h @ Wo
    k4b_g<<<32, 256>>>(ao1, ao2);                  // g1,g2 + exps
    k5_attn2<<<dim3(32, 4), 256>>>(adj, out);      // layer-2 attention -> out
}